// round 2
// baseline (speedup 1.0000x reference)
#include <cuda_runtime.h>
#include <math.h>

#define MAXN 4096
#define D    128

// ---------------- scratch (device globals; no allocation allowed) -------------
__device__ float g_S[(size_t)MAXN * MAXN];   // exp(sim/tau), masked entries = 0
__device__ float g_hnn[MAXN * D];            // normalized hard_neg rows
__device__ float g_pos[MAXN];                // exp(cos(hp_x, hp_qx)/tau)
__device__ float g_loss[MAXN];
__device__ int   g_q[MAXN];                  // positive-pair partner (involution)

// ---------------- K0: build partner map ---------------------------------------
__global__ void build_q_kernel(const int* __restrict__ pp, int npairs) {
    int r = blockIdx.x * blockDim.x + threadIdx.x;
    if (r < npairs) g_q[pp[2 * r]] = pp[2 * r + 1];
}

// ---------------- K1: hnn (normalized hard_neg) + pos per row -----------------
// one block (128 threads) per row
__global__ void prep_kernel(const float* __restrict__ emb, int N) {
    int x = blockIdx.x;
    int d = threadIdx.x;
    int qx = g_q[x];
    int fx = N - 1;
    while (fx == x || fx == qx) fx--;   // largest index not in {x, q[x]}

    float a  = emb[(size_t)x  * D + d];
    float b  = emb[(size_t)qx * D + d];
    float pf = emb[(size_t)fx * D + d];
    float h  = 0.5f * (a + pf);

    float v0 = h * h, v1 = a * a, v2 = b * b, v3 = a * b;
    __shared__ float sh[4][4];
    int lane = d & 31, w = d >> 5;
    #pragma unroll
    for (int o = 16; o; o >>= 1) {
        v0 += __shfl_xor_sync(0xffffffffu, v0, o);
        v1 += __shfl_xor_sync(0xffffffffu, v1, o);
        v2 += __shfl_xor_sync(0xffffffffu, v2, o);
        v3 += __shfl_xor_sync(0xffffffffu, v3, o);
    }
    if (lane == 0) { sh[0][w] = v0; sh[1][w] = v1; sh[2][w] = v2; sh[3][w] = v3; }
    __syncthreads();
    float nn = sh[0][0] + sh[0][1] + sh[0][2] + sh[0][3];
    float inv = 1.0f / fmaxf(sqrtf(nn), 1e-8f);
    g_hnn[(size_t)x * D + d] = h * inv;

    if (d == 0) {
        float aa = sh[1][0] + sh[1][1] + sh[1][2] + sh[1][3];
        float bb = sh[2][0] + sh[2][1] + sh[2][2] + sh[2][3];
        float ab = sh[3][0] + sh[3][1] + sh[3][2] + sh[3][3];
        // hp_x = 1.5a - 0.5b ; hp_y = 1.5b - 0.5a
        float dot = 2.5f * ab - 0.75f * (aa + bb);
        float nxx = 2.25f * aa + 0.25f * bb - 1.5f * ab;
        float nyy = 2.25f * bb + 0.25f * aa - 1.5f * ab;
        float nx = fmaxf(sqrtf(nxx), 1e-8f);
        float ny = fmaxf(sqrtf(nyy), 1e-8f);
        g_pos[x] = expf((dot / (nx * ny)) * 5.0f);
    }
}

// ---------------- K2: symmetric tiled SGEMM + exp + mask ----------------------
// 128x128 tile per CTA, upper triangle only, mirror store. 256 threads, 8x8/thread.
__global__ void __launch_bounds__(256) gemm_exp_kernel(int N) {
    extern __shared__ float smem[];
    float* As = smem;                 // [K=128][M=128]
    float* Bs = smem + 128 * 128;     // [K=128][N=128]

    int nb = N >> 7;
    int bid = blockIdx.x;
    int bi = 0, rem = bid;
    while (rem >= nb - bi) { rem -= nb - bi; bi++; }
    int bj = bi + rem;                // bj >= bi

    int tid = threadIdx.x;
    int r  = tid & 127;               // row within tile
    int ch = (tid >> 7) * 4;          // 0 or 4 (float offset within 8-col group)

    const float* Ag = g_hnn + (size_t)(bi * 128 + r) * D;
    const float* Bg = g_hnn + (size_t)(bj * 128 + r) * D;
    #pragma unroll
    for (int it = 0; it < 16; ++it) {
        int c = it * 8 + ch;
        float4 va = *(const float4*)(Ag + c);
        float4 vb = *(const float4*)(Bg + c);
        As[(c + 0) * 128 + r] = va.x; As[(c + 1) * 128 + r] = va.y;
        As[(c + 2) * 128 + r] = va.z; As[(c + 3) * 128 + r] = va.w;
        Bs[(c + 0) * 128 + r] = vb.x; Bs[(c + 1) * 128 + r] = vb.y;
        Bs[(c + 2) * 128 + r] = vb.z; Bs[(c + 3) * 128 + r] = vb.w;
    }
    __syncthreads();

    int ty = tid >> 4, tx = tid & 15;
    float acc[8][8];
    #pragma unroll
    for (int i = 0; i < 8; i++)
        #pragma unroll
        for (int j = 0; j < 8; j++) acc[i][j] = 0.0f;

    const float4* A4 = (const float4*)As;
    const float4* B4 = (const float4*)Bs;
    #pragma unroll 4
    for (int k = 0; k < 128; k++) {
        float4 a0 = A4[k * 32 + ty * 2];
        float4 a1 = A4[k * 32 + ty * 2 + 1];
        float4 b0 = B4[k * 32 + tx * 2];
        float4 b1 = B4[k * 32 + tx * 2 + 1];
        float av[8] = {a0.x, a0.y, a0.z, a0.w, a1.x, a1.y, a1.z, a1.w};
        float bv[8] = {b0.x, b0.y, b0.z, b0.w, b1.x, b1.y, b1.z, b1.w};
        #pragma unroll
        for (int i = 0; i < 8; i++)
            #pragma unroll
            for (int j = 0; j < 8; j++)
                acc[i][j] += av[i] * bv[j];
    }

    int m0 = bi * 128 + ty * 8;
    int n0 = bj * 128 + tx * 8;
    int qm[8];
    #pragma unroll
    for (int i = 0; i < 8; i++) qm[i] = g_q[m0 + i];

    #pragma unroll
    for (int i = 0; i < 8; i++)
        #pragma unroll
        for (int j = 0; j < 8; j++) {
            int m = m0 + i, n = n0 + j;
            float v = (n == m || n == qm[i]) ? 0.0f : expf(acc[i][j] * 5.0f);
            acc[i][j] = v;
        }

    // normal store S[m][n]
    #pragma unroll
    for (int i = 0; i < 8; i++) {
        float4 p0 = make_float4(acc[i][0], acc[i][1], acc[i][2], acc[i][3]);
        float4 p1 = make_float4(acc[i][4], acc[i][5], acc[i][6], acc[i][7]);
        float* dst = g_S + (size_t)(m0 + i) * N + n0;
        *(float4*)(dst)     = p0;
        *(float4*)(dst + 4) = p1;
    }
    // mirror store S[n][m] (symmetric; bitwise-identical on diagonal blocks)
    #pragma unroll
    for (int j = 0; j < 8; j++) {
        float4 p0 = make_float4(acc[0][j], acc[1][j], acc[2][j], acc[3][j]);
        float4 p1 = make_float4(acc[4][j], acc[5][j], acc[6][j], acc[7][j]);
        float* dst = g_S + (size_t)(n0 + j) * N + m0;
        *(float4*)(dst)     = p0;
        *(float4*)(dst + 4) = p1;
    }
}

// ---------------- K3: per-row exact radix select + thresholded sum -------------
// one CTA (256 threads) per row. Values are exp(.) >= 0, so float bits are
// order-preserving as uint32. 3-level select: bits [31:21],[20:10],[9:0].
__global__ void __launch_bounds__(256) select_kernel(const int* __restrict__ stage_ptr,
                                                     int N, int rank) {
    extern __shared__ unsigned smem_u[];
    unsigned* vals = smem_u;            // N
    unsigned* hist = smem_u + N;        // 2048
    __shared__ unsigned s_warp[8];
    __shared__ int s_bin, s_krem;
    __shared__ float s_red[8];

    int x = blockIdx.x, tid = threadIdx.x;
    const float4* row4 = (const float4*)(g_S + (size_t)x * N);
    for (int i = tid; i < (N >> 2); i += 256) {
        float4 v = row4[i];
        vals[4 * i + 0] = __float_as_uint(v.x);
        vals[4 * i + 1] = __float_as_uint(v.y);
        vals[4 * i + 2] = __float_as_uint(v.z);
        vals[4 * i + 3] = __float_as_uint(v.w);
    }
    __syncthreads();

    int stage = *stage_ptr;
    float ssum = 0.0f;

    if (stage) {
        unsigned prefix = 0;
        int k = rank;
        int prevShift = 32;
        #pragma unroll
        for (int L = 0; L < 3; ++L) {
            const int nbins = (L == 2) ? 1024 : 2048;
            const int sh    = (L == 0) ? 21 : (L == 1) ? 10 : 0;
            const unsigned dmask = nbins - 1;

            for (int i = tid; i < nbins; i += 256) hist[i] = 0;
            __syncthreads();
            for (int i = tid; i < N; i += 256) {
                unsigned key = vals[i];
                if (L == 0 || (key >> prevShift) == prefix)
                    atomicAdd(&hist[(key >> sh) & dmask], 1u);
            }
            __syncthreads();

            const int per = nbins >> 8;   // 8 or 4 bins per thread
            unsigned local = 0;
            for (int b = 0; b < per; b++) local += hist[tid * per + b];

            unsigned inc = local;
            int lane = tid & 31, w = tid >> 5;
            #pragma unroll
            for (int o = 1; o < 32; o <<= 1) {
                unsigned t = __shfl_up_sync(0xffffffffu, inc, o);
                if (lane >= o) inc += t;
            }
            if (lane == 31) s_warp[w] = inc;
            __syncthreads();
            unsigned woff = 0;
            for (int ww = 0; ww < w; ++ww) woff += s_warp[ww];
            unsigned excl = woff + inc - local;

            unsigned uk = (unsigned)k;
            if (excl <= uk && uk < excl + local) {
                unsigned c = excl;
                for (int b = 0; b < per; b++) {
                    unsigned h = hist[tid * per + b];
                    if (uk < c + h) { s_bin = tid * per + b; s_krem = (int)(uk - c); break; }
                    c += h;
                }
            }
            __syncthreads();
            int dsel = s_bin;
            k = s_krem;
            prefix = (prefix << ((L == 2) ? 10 : 11)) | (unsigned)dsel;
            prevShift = sh;
            __syncthreads();
        }
        float t = __uint_as_float(prefix);   // exact rank-th smallest value
        for (int i = tid; i < N; i += 256) {
            float v = __uint_as_float(vals[i]);
            if (v >= t) ssum += v;
        }
    } else {
        for (int i = tid; i < N; i += 256) ssum += __uint_as_float(vals[i]);
    }

    int lane = tid & 31, w = tid >> 5;
    #pragma unroll
    for (int o = 16; o; o >>= 1) ssum += __shfl_xor_sync(0xffffffffu, ssum, o);
    if (lane == 0) s_red[w] = ssum;
    __syncthreads();
    if (tid == 0) {
        float tot = 0.0f;
        #pragma unroll
        for (int ww = 0; ww < 8; ++ww) tot += s_red[ww];
        float pos = g_pos[x];
        g_loss[x] = -logf(pos / (pos + tot));
    }
}

// ---------------- K4: deterministic mean reduce --------------------------------
__global__ void reduce_kernel(float* __restrict__ out, int N) {
    __shared__ float s_red[8];
    int tid = threadIdx.x;
    float s = 0.0f;
    for (int i = tid; i < N; i += 256) s += g_loss[i];
    int lane = tid & 31, w = tid >> 5;
    #pragma unroll
    for (int o = 16; o; o >>= 1) s += __shfl_xor_sync(0xffffffffu, s, o);
    if (lane == 0) s_red[w] = s;
    __syncthreads();
    if (tid == 0) {
        float tot = 0.0f;
        #pragma unroll
        for (int ww = 0; ww < 8; ++ww) tot += s_red[ww];
        out[0] = tot / (float)N;
    }
}

// ---------------- launch --------------------------------------------------------
extern "C" void kernel_launch(void* const* d_in, const int* in_sizes, int n_in,
                              void* d_out, int out_size) {
    const float* emb   = (const float*)d_in[0];
    const int*   pp    = (const int*)d_in[1];
    const int*   stage = (const int*)d_in[2];

    int N      = in_sizes[0] / D;        // 4096
    int npairs = in_sizes[1] / 2;        // 4096

    build_q_kernel<<<(npairs + 255) / 256, 256>>>(pp, npairs);
    prep_kernel<<<N, D>>>(emb, N);

    int nb   = N >> 7;
    int nblk = nb * (nb + 1) / 2;
    cudaFuncSetAttribute(gemm_exp_kernel,
                         cudaFuncAttributeMaxDynamicSharedMemorySize, 131072);
    gemm_exp_kernel<<<nblk, 256, 131072>>>(N);

    int rank = (int)(0.8 * (double)(N - 1) + 1e-9);   // 3276 for N=4096
    size_t sm3 = (size_t)N * 4 + 2048 * 4;
    select_kernel<<<N, 256, sm3>>>(stage, N, rank);

    reduce_kernel<<<1, 256>>>((float*)d_out, N);
}

// round 3
// speedup vs baseline: 1.0726x; 1.0726x over previous
#include <cuda_runtime.h>
#include <math.h>

#define MAXN 4096
#define D    128

// ---------------- scratch (device globals; no allocation allowed) -------------
__device__ float g_S[(size_t)MAXN * MAXN];   // exp(sim/tau), masked entries = 0
__device__ float g_hnn[MAXN * D];            // normalized hard_neg rows
__device__ float g_pos[MAXN];                // exp(cos(hp_x, hp_qx)/tau)
__device__ float g_loss[MAXN];
__device__ int   g_q[MAXN];                  // positive-pair partner (involution)

// ---------------- K0: build partner map ---------------------------------------
__global__ void build_q_kernel(const int* __restrict__ pp, int npairs) {
    int r = blockIdx.x * blockDim.x + threadIdx.x;
    if (r < npairs) g_q[pp[2 * r]] = pp[2 * r + 1];
}

// ---------------- K1: hnn (normalized hard_neg) + pos per row -----------------
// one block (128 threads) per row
__global__ void prep_kernel(const float* __restrict__ emb, int N) {
    int x = blockIdx.x;
    int d = threadIdx.x;
    int qx = g_q[x];
    int fx = N - 1;
    while (fx == x || fx == qx) fx--;   // largest index not in {x, q[x]}

    float a  = emb[(size_t)x  * D + d];
    float b  = emb[(size_t)qx * D + d];
    float pf = emb[(size_t)fx * D + d];
    float h  = 0.5f * (a + pf);

    float v0 = h * h, v1 = a * a, v2 = b * b, v3 = a * b;
    __shared__ float sh[4][4];
    int lane = d & 31, w = d >> 5;
    #pragma unroll
    for (int o = 16; o; o >>= 1) {
        v0 += __shfl_xor_sync(0xffffffffu, v0, o);
        v1 += __shfl_xor_sync(0xffffffffu, v1, o);
        v2 += __shfl_xor_sync(0xffffffffu, v2, o);
        v3 += __shfl_xor_sync(0xffffffffu, v3, o);
    }
    if (lane == 0) { sh[0][w] = v0; sh[1][w] = v1; sh[2][w] = v2; sh[3][w] = v3; }
    __syncthreads();
    float nn = sh[0][0] + sh[0][1] + sh[0][2] + sh[0][3];
    float inv = 1.0f / fmaxf(sqrtf(nn), 1e-8f);
    g_hnn[(size_t)x * D + d] = h * inv;

    if (d == 0) {
        float aa = sh[1][0] + sh[1][1] + sh[1][2] + sh[1][3];
        float bb = sh[2][0] + sh[2][1] + sh[2][2] + sh[2][3];
        float ab = sh[3][0] + sh[3][1] + sh[3][2] + sh[3][3];
        // hp_x = 1.5a - 0.5b ; hp_y = 1.5b - 0.5a
        float dot = 2.5f * ab - 0.75f * (aa + bb);
        float nxx = 2.25f * aa + 0.25f * bb - 1.5f * ab;
        float nyy = 2.25f * bb + 0.25f * aa - 1.5f * ab;
        float nx = fmaxf(sqrtf(nxx), 1e-8f);
        float ny = fmaxf(sqrtf(nyy), 1e-8f);
        g_pos[x] = expf((dot / (nx * ny)) * 5.0f);
    }
}

// ---------------- K2: symmetric tiled SGEMM + exp + mask ----------------------
// 128x128 tile per CTA, upper triangle only, mirror store. 256 threads, 8x8/thread.
// K staged in 2 chunks of 64 -> 64KB smem -> 2 CTAs/SM for latency hiding.
__global__ void __launch_bounds__(256, 2) gemm_exp_kernel(int N) {
    extern __shared__ float smem[];
    float* As = smem;                 // [K=64][M=128]
    float* Bs = smem + 64 * 128;      // [K=64][N=128]

    int nb = N >> 7;
    int bid = blockIdx.x;
    int bi = 0, rem = bid;
    while (rem >= nb - bi) { rem -= nb - bi; bi++; }
    int bj = bi + rem;                // bj >= bi

    int tid  = threadIdx.x;
    int r    = tid & 127;             // row within tile
    int half = tid >> 7;              // 0 or 1

    const float* Ag = g_hnn + (size_t)(bi * 128 + r) * D;
    const float* Bg = g_hnn + (size_t)(bj * 128 + r) * D;

    int ty = tid >> 4, tx = tid & 15;
    float acc[8][8];
    #pragma unroll
    for (int i = 0; i < 8; i++)
        #pragma unroll
        for (int j = 0; j < 8; j++) acc[i][j] = 0.0f;

    const float4* A4 = (const float4*)As;
    const float4* B4 = (const float4*)Bs;

    #pragma unroll
    for (int chunk = 0; chunk < 2; ++chunk) {
        int kb = chunk * 64;
        #pragma unroll
        for (int f = 0; f < 8; ++f) {
            int c  = kb + (half * 8 + f) * 4;   // global k-col
            int cl = c - kb;                    // local 0..60
            float4 va = *(const float4*)(Ag + c);
            float4 vb = *(const float4*)(Bg + c);
            As[(cl + 0) * 128 + r] = va.x; As[(cl + 1) * 128 + r] = va.y;
            As[(cl + 2) * 128 + r] = va.z; As[(cl + 3) * 128 + r] = va.w;
            Bs[(cl + 0) * 128 + r] = vb.x; Bs[(cl + 1) * 128 + r] = vb.y;
            Bs[(cl + 2) * 128 + r] = vb.z; Bs[(cl + 3) * 128 + r] = vb.w;
        }
        __syncthreads();

        #pragma unroll 4
        for (int k = 0; k < 64; k++) {
            float4 a0 = A4[k * 32 + ty * 2];
            float4 a1 = A4[k * 32 + ty * 2 + 1];
            float4 b0 = B4[k * 32 + tx * 2];
            float4 b1 = B4[k * 32 + tx * 2 + 1];
            float av[8] = {a0.x, a0.y, a0.z, a0.w, a1.x, a1.y, a1.z, a1.w};
            float bv[8] = {b0.x, b0.y, b0.z, b0.w, b1.x, b1.y, b1.z, b1.w};
            #pragma unroll
            for (int i = 0; i < 8; i++)
                #pragma unroll
                for (int j = 0; j < 8; j++)
                    acc[i][j] += av[i] * bv[j];
        }
        __syncthreads();
    }

    int m0 = bi * 128 + ty * 8;
    int n0 = bj * 128 + tx * 8;
    int qm[8];
    #pragma unroll
    for (int i = 0; i < 8; i++) qm[i] = g_q[m0 + i];

    #pragma unroll
    for (int i = 0; i < 8; i++)
        #pragma unroll
        for (int j = 0; j < 8; j++) {
            int m = m0 + i, n = n0 + j;
            float v = (n == m || n == qm[i]) ? 0.0f : __expf(acc[i][j] * 5.0f);
            acc[i][j] = v;
        }

    // normal store S[m][n]
    #pragma unroll
    for (int i = 0; i < 8; i++) {
        float4 p0 = make_float4(acc[i][0], acc[i][1], acc[i][2], acc[i][3]);
        float4 p1 = make_float4(acc[i][4], acc[i][5], acc[i][6], acc[i][7]);
        float* dst = g_S + (size_t)(m0 + i) * N + n0;
        *(float4*)(dst)     = p0;
        *(float4*)(dst + 4) = p1;
    }
    // mirror store S[n][m] (symmetric; bitwise-identical values)
    #pragma unroll
    for (int j = 0; j < 8; j++) {
        float4 p0 = make_float4(acc[0][j], acc[1][j], acc[2][j], acc[3][j]);
        float4 p1 = make_float4(acc[4][j], acc[5][j], acc[6][j], acc[7][j]);
        float* dst = g_S + (size_t)(n0 + j) * N + m0;
        *(float4*)(dst)     = p0;
        *(float4*)(dst + 4) = p1;
    }
}

// ---------------- K3 helper: locate bin containing rank k ----------------------
__device__ __forceinline__ void locate_bin(unsigned* hist, int nbins, unsigned k,
                                           unsigned* s_warp, int* s_bin, int* s_krem) {
    int tid = threadIdx.x;
    int per = nbins >> 8;
    unsigned local = 0;
    for (int b = 0; b < per; b++) local += hist[tid * per + b];
    unsigned inc = local;
    int lane = tid & 31, w = tid >> 5;
    #pragma unroll
    for (int o = 1; o < 32; o <<= 1) {
        unsigned t = __shfl_up_sync(0xffffffffu, inc, o);
        if (lane >= o) inc += t;
    }
    if (lane == 31) s_warp[w] = inc;
    __syncthreads();
    unsigned woff = 0;
    for (int ww = 0; ww < w; ++ww) woff += s_warp[ww];
    unsigned excl = woff + inc - local;
    if (excl <= k && k < excl + local) {
        unsigned c = excl;
        for (int b = 0; b < per; b++) {
            unsigned h = hist[tid * per + b];
            if (k < c + h) { *s_bin = tid * per + b; *s_krem = (int)(k - c); break; }
            c += h;
        }
    }
    __syncthreads();
}

// ---------------- K3: per-row exact radix select + thresholded sum -------------
// one CTA (256 threads) per row. Values kept in registers (16/thread).
// L0: 2048-bin hist on bits[31:21] over all 4096; compact rank-bin candidates
// to smem; L1/L2 refine over candidates only; final sum from registers.
__global__ void __launch_bounds__(256) select_kernel(const int* __restrict__ stage_ptr,
                                                     int N, int rank) {
    __shared__ unsigned hist[2048];
    __shared__ float    cand[4096];
    __shared__ unsigned s_warp[8];
    __shared__ int      s_bin, s_krem, s_cnt;
    __shared__ float    s_red[8];

    int x = blockIdx.x, tid = threadIdx.x;
    const float4* row4 = (const float4*)(g_S + (size_t)x * N);
    float v[16];
    #pragma unroll
    for (int j = 0; j < 4; ++j) {
        float4 t4 = row4[tid + 256 * j];
        v[4 * j + 0] = t4.x; v[4 * j + 1] = t4.y;
        v[4 * j + 2] = t4.z; v[4 * j + 3] = t4.w;
    }

    int stage = *stage_ptr;
    float ssum = 0.0f;

    if (stage) {
        // ---- L0 histogram on bits[31:21] ----
        #pragma unroll
        for (int i = 0; i < 8; ++i) hist[tid + 256 * i] = 0;
        if (tid == 0) s_cnt = 0;
        __syncthreads();
        #pragma unroll
        for (int j = 0; j < 16; ++j)
            atomicAdd(&hist[__float_as_uint(v[j]) >> 21], 1u);
        __syncthreads();
        locate_bin(hist, 2048, (unsigned)rank, s_warp, &s_bin, &s_krem);
        int b0 = s_bin;
        unsigned krem = (unsigned)s_krem;
        unsigned lo = (unsigned)b0 << 21;
        unsigned hi = lo + (1u << 21);
        __syncthreads();

        // ---- compact rank-bin candidates ----
        #pragma unroll
        for (int j = 0; j < 16; ++j) {
            unsigned key = __float_as_uint(v[j]);
            if (key >= lo && key < hi) {
                int p = atomicAdd(&s_cnt, 1);
                cand[p] = v[j];
            }
        }
        __syncthreads();
        int M = s_cnt;

        // ---- L1 histogram on bits[20:10] over candidates ----
        #pragma unroll
        for (int i = 0; i < 8; ++i) hist[tid + 256 * i] = 0;
        __syncthreads();
        for (int i = tid; i < M; i += 256)
            atomicAdd(&hist[(__float_as_uint(cand[i]) >> 10) & 2047u], 1u);
        __syncthreads();
        locate_bin(hist, 2048, krem, s_warp, &s_bin, &s_krem);
        unsigned b1 = (unsigned)s_bin;
        unsigned krem1 = (unsigned)s_krem;
        __syncthreads();

        // ---- L2 histogram on bits[9:0] over candidates in bin b1 ----
        #pragma unroll
        for (int i = 0; i < 4; ++i) hist[tid + 256 * i] = 0;
        __syncthreads();
        for (int i = tid; i < M; i += 256) {
            unsigned key = __float_as_uint(cand[i]);
            if (((key >> 10) & 2047u) == b1)
                atomicAdd(&hist[key & 1023u], 1u);
        }
        __syncthreads();
        locate_bin(hist, 1024, krem1, s_warp, &s_bin, &s_krem);
        unsigned b2 = (unsigned)s_bin;

        float t = __uint_as_float(lo | (b1 << 10) | b2);   // exact rank-th smallest
        #pragma unroll
        for (int j = 0; j < 16; ++j)
            if (v[j] >= t) ssum += v[j];
    } else {
        #pragma unroll
        for (int j = 0; j < 16; ++j) ssum += v[j];
    }

    int lane = tid & 31, w = tid >> 5;
    #pragma unroll
    for (int o = 16; o; o >>= 1) ssum += __shfl_xor_sync(0xffffffffu, ssum, o);
    if (lane == 0) s_red[w] = ssum;
    __syncthreads();
    if (tid == 0) {
        float tot = 0.0f;
        #pragma unroll
        for (int ww = 0; ww < 8; ++ww) tot += s_red[ww];
        float pos = g_pos[x];
        g_loss[x] = -logf(pos / (pos + tot));
    }
}

// ---------------- K4: deterministic mean reduce --------------------------------
__global__ void reduce_kernel(float* __restrict__ out, int N) {
    __shared__ float s_red[8];
    int tid = threadIdx.x;
    float s = 0.0f;
    for (int i = tid; i < N; i += 256) s += g_loss[i];
    int lane = tid & 31, w = tid >> 5;
    #pragma unroll
    for (int o = 16; o; o >>= 1) s += __shfl_xor_sync(0xffffffffu, s, o);
    if (lane == 0) s_red[w] = s;
    __syncthreads();
    if (tid == 0) {
        float tot = 0.0f;
        #pragma unroll
        for (int ww = 0; ww < 8; ++ww) tot += s_red[ww];
        out[0] = tot / (float)N;
    }
}

// ---------------- launch --------------------------------------------------------
extern "C" void kernel_launch(void* const* d_in, const int* in_sizes, int n_in,
                              void* d_out, int out_size) {
    const float* emb   = (const float*)d_in[0];
    const int*   pp    = (const int*)d_in[1];
    const int*   stage = (const int*)d_in[2];

    int N      = in_sizes[0] / D;        // 4096
    int npairs = in_sizes[1] / 2;        // 4096

    build_q_kernel<<<(npairs + 255) / 256, 256>>>(pp, npairs);
    prep_kernel<<<N, D>>>(emb, N);

    int nb   = N >> 7;
    int nblk = nb * (nb + 1) / 2;
    cudaFuncSetAttribute(gemm_exp_kernel,
                         cudaFuncAttributeMaxDynamicSharedMemorySize, 65536);
    gemm_exp_kernel<<<nblk, 256, 65536>>>(N);

    int rank = (int)(0.8 * (double)(N - 1) + 1e-9);   // 3276 for N=4096
    select_kernel<<<N, 256>>>(stage, N, rank);

    reduce_kernel<<<1, 256>>>((float*)d_out, N);
}